// round 15
// baseline (speedup 1.0000x reference)
#include <cuda_runtime.h>
#include <cstdint>

#define BATCH 8
#define SEQ   2048
#define DIM   64
#define TM    64
#define TN    32
#define NTILES (SEQ/TN)   // 64
#define NTHR  256

// ---- smem layout (float offsets) ----
// K frag buffer: 32 keys x 33 float4 (32 data + 1 pad) = 4224 floats per buf
// V frag buffer: 4 groups x 128 float4 = 2048 floats per buf
#define KBUF4 1056
#define VBUF4 512
#define F_K   0
#define F_V   8448
#define F_SE  12544
#define F_MSK 14848
#define F_RS  16896
#define F_INV 17024
#define SMEM_FLOATS 17088
#define SMEM_BYTES (SMEM_FLOATS*4)
#define EST 36

// fragment-major scratch:
// g_kfrag[key][c4][ks] = {Khi[ks*8+c4], Khi[ks*8+c4+4], Klo[...], Klo[...]}
// g_vfrag[group][mt][r4][c4] = {Vt_hi[m][k], Vt_hi[m+8][k], Vt_hi[m][k+4], Vt_hi[m+8][k+4]}
__device__ float4 g_kfrag[BATCH*SEQ*32];
__device__ float4 g_vfrag[BATCH*SEQ*16];

__device__ __forceinline__ uint32_t tf32u(float x) {
    uint32_t u; asm("cvt.rna.tf32.f32 %0, %1;" : "=r"(u) : "f"(x)); return u;
}
__device__ __forceinline__ float uf(uint32_t u) { return __uint_as_float(u); }
__device__ __forceinline__ uint32_t fu(float f) { return __float_as_uint(f); }
__device__ __forceinline__ uint32_t s2u(const void* p) {
    uint32_t a;
    asm("{ .reg .u64 t; cvta.to.shared.u64 t, %1; cvt.u32.u64 %0, t; }" : "=r"(a) : "l"(p));
    return a;
}

#define CP16(dst, src) asm volatile("cp.async.ca.shared.global [%0], [%1], 16;" \
                                    :: "r"(dst), "l"(src) : "memory")
#define CP_COMMIT() asm volatile("cp.async.commit_group;" ::: "memory")
#define CP_WAIT0()  asm volatile("cp.async.wait_group 0;" ::: "memory")

__device__ __forceinline__ void mma8(float* c, const uint32_t* a, uint32_t b0, uint32_t b1) {
    asm volatile("mma.sync.aligned.m16n8k8.row.col.f32.tf32.tf32.f32 "
        "{%0,%1,%2,%3},{%4,%5,%6,%7},{%8,%9},{%0,%1,%2,%3};"
        : "+f"(c[0]), "+f"(c[1]), "+f"(c[2]), "+f"(c[3])
        : "r"(a[0]), "r"(a[1]), "r"(a[2]), "r"(a[3]), "r"(b0), "r"(b1));
}

// ---- prologue: pack K (hi+lo) and V (hi) into fragment-major gmem ----
__global__ void __launch_bounds__(256)
pack_k_kernel(const float* __restrict__ key)
{
    int i = blockIdx.x * 256 + threadIdx.x;      // f4 idx < BATCH*SEQ*32
    int bk = i >> 5, r = i & 31, c4 = r >> 3, ks = r & 7;
    float a = key[(size_t)bk * 64 + ks * 8 + c4];
    float bb = key[(size_t)bk * 64 + ks * 8 + c4 + 4];
    float ha = uf(tf32u(a)), hb = uf(tf32u(bb));
    g_kfrag[i] = make_float4(ha, hb, a - ha, bb - hb);
}
__global__ void __launch_bounds__(256)
pack_v_kernel(const float* __restrict__ value)
{
    int i = blockIdx.x * 256 + threadIdx.x;      // f4 idx < BATCH*SEQ*16
    int g = i >> 7, r = i & 127, mt = r >> 5, rr = r & 31, r4 = rr >> 2, c4 = rr & 3;
    const float* vb = value + (size_t)g * 8 * 64;
    float x0 = vb[c4 * 64 + mt * 16 + r4];
    float x1 = vb[c4 * 64 + mt * 16 + r4 + 8];
    float x2 = vb[(c4 + 4) * 64 + mt * 16 + r4];
    float x3 = vb[(c4 + 4) * 64 + mt * 16 + r4 + 8];
    g_vfrag[i] = make_float4(uf(tf32u(x0)), uf(tf32u(x1)), uf(tf32u(x2)), uf(tf32u(x3)));
}

// stage fragment tile nt via cp.async into buffer nt&1
__device__ __forceinline__ void stage(uint32_t sb, int b, int nt, int t) {
    const int buf = nt & 1;
    const float4* ksrc = g_kfrag + ((size_t)b * SEQ + nt * TN) * 32;
    const float4* vsrc = g_vfrag + (size_t)b * SEQ * 16 + (size_t)nt * 512;
    #pragma unroll
    for (int i = 0; i < 4; i++) {
        int idx = t + NTHR * i;                  // 0..1023
        int kk = idx >> 5, j = idx & 31;
        CP16(sb + (buf * KBUF4 + kk * 33 + j) * 16, ksrc + idx);
    }
    #pragma unroll
    for (int i = 0; i < 2; i++) {
        int idx = t + NTHR * i;                  // 0..511
        CP16(sb + F_V * 4 + (buf * VBUF4 + idx) * 16, vsrc + idx);
    }
}

__global__ void __launch_bounds__(NTHR, 2)
attn_mma_kernel(const float* __restrict__ query,
                const int*   __restrict__ qmask,
                float* __restrict__ out_ctx,
                float*              out_attn)
{
    extern __shared__ float sm[];
    const uint32_t sb = s2u(sm);
    const int b  = blockIdx.y;
    const int q0 = blockIdx.x * TM;
    const int t  = threadIdx.x;
    const int w  = t >> 5;
    const int wqg = w >> 1;          // q group 0..3 (16 rows each)
    const int kh  = w & 1;           // key half 0/1 (16 keys each)
    const int lane = t & 31;
    const int r4 = lane >> 2;        // 0..7
    const int c4 = lane & 3;         // 0..3

    float* attn_base = out_attn + ((size_t)b * SEQ + q0) * SEQ;

    // ---- stage tile 0 (async), mask ----
    stage(sb, b, 0, t);
    CP_COMMIT();
    {
        const int* mg = qmask + (size_t)b * SEQ;
        float* msk = sm + F_MSK;
        #pragma unroll
        for (int i = t; i < SEQ; i += NTHR)
            msk[i] = mg[i] ? -1e30f : 0.0f;
    }

    // ---- persistent Q frags (hi only, scaled 0.125) ----
    uint32_t qh[8][4];
    {
        const float* qr = query + ((size_t)b * SEQ + q0 + 16 * wqg) * DIM;
        #pragma unroll
        for (int ks = 0; ks < 8; ks++) {
            qh[ks][0] = tf32u(qr[(size_t)r4 * DIM + ks * 8 + c4] * 0.125f);
            qh[ks][1] = tf32u(qr[(size_t)(r4 + 8) * DIM + ks * 8 + c4] * 0.125f);
            qh[ks][2] = tf32u(qr[(size_t)r4 * DIM + ks * 8 + c4 + 4] * 0.125f);
            qh[ks][3] = tf32u(qr[(size_t)(r4 + 8) * DIM + ks * 8 + c4 + 4] * 0.125f);
        }
    }

    float cacc[4][2][4];             // ctx^T partial over this key half
    #pragma unroll
    for (int mt = 0; mt < 4; mt++)
        #pragma unroll
        for (int nq = 0; nq < 2; nq++)
            #pragma unroll
            for (int i = 0; i < 4; i++) cacc[mt][nq][i] = 0.0f;
    float rs0 = 0.0f, rs8 = 0.0f;

    float* sE = sm + F_SE;
    const float* msk = sm + F_MSK;

    for (int kt = 0; kt < NTILES; kt++) {
        const int buf = kt & 1;
        CP_WAIT0();
        __syncthreads();             // tile kt visible; prev compute done
        if (kt + 1 < NTILES) {
            stage(sb, b, kt + 1, t);
            CP_COMMIT();
        }

        // ---- QK^T: S[16q x 16key(half)], 2-term tf32, frag-major LDS.128 ----
        float sacc[2][4];
        #pragma unroll
        for (int nt = 0; nt < 2; nt++)
            #pragma unroll
            for (int i = 0; i < 4; i++) sacc[nt][i] = 0.0f;

        const float4* kf = (const float4*)sm + buf * KBUF4
                         + (kh * 16 + r4) * 33 + c4 * 8;
        #pragma unroll
        for (int ks = 0; ks < 8; ks++) {
            #pragma unroll
            for (int nt = 0; nt < 2; nt++) {
                float4 f = kf[nt * 264 + ks];
                mma8(sacc[nt], qh[ks], fu(f.x), fu(f.y));
                mma8(sacc[nt], qh[ks], fu(f.z), fu(f.w));
            }
        }

        // ---- epilogue: exp+mask -> gmem + sE, rowsum ----
        {
            float* ar0 = attn_base + (size_t)(16 * wqg + r4) * SEQ + kt * TN;
            float* ar8 = ar0 + (size_t)8 * SEQ;
            float* se0 = sE + (16 * wqg + r4) * EST;
            float* se8 = se0 + 8 * EST;
            #pragma unroll
            for (int nt = 0; nt < 2; nt++) {
                int kloc = kh * 16 + nt * 8 + 2 * c4;
                float m0 = msk[kt * TN + kloc];
                float m1 = msk[kt * TN + kloc + 1];
                float e0 = __expf(sacc[nt][0] + m0);
                float e1 = __expf(sacc[nt][1] + m1);
                float e2 = __expf(sacc[nt][2] + m0);
                float e3 = __expf(sacc[nt][3] + m1);
                rs0 += e0 + e1; rs8 += e2 + e3;
                *(float2*)(ar0 + kloc) = make_float2(e0, e1);
                *(float2*)(ar8 + kloc) = make_float2(e2, e3);
                *(float2*)(se0 + kloc) = make_float2(e0, e1);
                *(float2*)(se8 + kloc) = make_float2(e2, e3);
            }
        }
        __syncwarp();

        // ---- PV (transposed, own key half, 1-term): ctx^T += Vhi^T * Phi^T ----
        {
            const float4* vf = (const float4*)sm + F_V / 4 + buf * VBUF4
                             + (kh * 2) * 128 + r4 * 4 + c4;
            const float* se_b = sE + (16 * wqg + r4) * EST + kh * 16 + c4;
            #pragma unroll
            for (int ks = 0; ks < 2; ks++) {
                uint32_t bh[2][2];
                #pragma unroll
                for (int nq = 0; nq < 2; nq++) {
                    bh[nq][0] = tf32u(se_b[nq * 8 * EST + ks * 8]);
                    bh[nq][1] = tf32u(se_b[nq * 8 * EST + ks * 8 + 4]);
                }
                #pragma unroll
                for (int mt = 0; mt < 4; mt++) {
                    float4 a = vf[ks * 128 + mt * 32];
                    uint32_t ah[4] = {fu(a.x), fu(a.y), fu(a.z), fu(a.w)};
                    #pragma unroll
                    for (int nq = 0; nq < 2; nq++)
                        mma8(cacc[mt][nq], ah, bh[nq][0], bh[nq][1]);
                }
            }
        }
    }
    __syncthreads();

    // ---- rowsum: quad-reduce, write per-half partials ----
    rs0 += __shfl_xor_sync(0xffffffffu, rs0, 1);
    rs0 += __shfl_xor_sync(0xffffffffu, rs0, 2);
    rs8 += __shfl_xor_sync(0xffffffffu, rs8, 1);
    rs8 += __shfl_xor_sync(0xffffffffu, rs8, 2);
    if (c4 == 0) {
        sm[F_RS + (16 * wqg + r4) * 2 + kh]     = rs0;
        sm[F_RS + (16 * wqg + r4 + 8) * 2 + kh] = rs8;
    }
    // ---- odd warps dump ctx partials (reuse K area) ----
    if (kh == 1) {
        float* dst = sm + F_K + wqg * 1024 + lane * 32;
        #pragma unroll
        for (int mt = 0; mt < 4; mt++)
            #pragma unroll
            for (int nq = 0; nq < 2; nq++)
                #pragma unroll
                for (int i = 0; i < 4; i++)
                    dst[mt * 8 + nq * 4 + i] = cacc[mt][nq][i];
    }
    __syncthreads();

    if (t < TM) sm[F_INV + t] = 1.0f / (sm[F_RS + t * 2] + sm[F_RS + t * 2 + 1]);
    if (kh == 0) {
        const float* src = sm + F_K + wqg * 1024 + lane * 32;
        #pragma unroll
        for (int mt = 0; mt < 4; mt++)
            #pragma unroll
            for (int nq = 0; nq < 2; nq++)
                #pragma unroll
                for (int i = 0; i < 4; i++)
                    cacc[mt][nq][i] += src[mt * 8 + nq * 4 + i];
    }
    __syncthreads();

    // ---- ctx out (even warps, normalized) ----
    if (kh == 0) {
        const float* sInv = sm + F_INV;
        #pragma unroll
        for (int nq = 0; nq < 2; nq++) {
            int qloc = 16 * wqg + nq * 8 + 2 * c4;
            float i0 = sInv[qloc], i1 = sInv[qloc + 1];
            float* o0 = out_ctx + ((size_t)b * SEQ + q0 + qloc) * DIM;
            float* o1 = o0 + DIM;
            #pragma unroll
            for (int mt = 0; mt < 4; mt++) {
                int dimr = mt * 16 + r4;
                o0[dimr]     = cacc[mt][nq][0] * i0;
                o1[dimr]     = cacc[mt][nq][1] * i1;
                o0[dimr + 8] = cacc[mt][nq][2] * i0;
                o1[dimr + 8] = cacc[mt][nq][3] * i1;
            }
        }
    }

    // ---- normalize this CTA's attn slab in place (L2-hot) ----
    {
        const float* sInv = sm + F_INV;
        #pragma unroll 4
        for (int i = t; i < TM * SEQ / 4; i += NTHR) {
            int r = i >> 9;            // / (SEQ/4)
            int c = i & 511;
            float inv = sInv[r];
            float4* p = (float4*)(attn_base + (size_t)r * SEQ) + c;
            float4 v = *p;
            v.x *= inv; v.y *= inv; v.z *= inv; v.w *= inv;
            *p = v;
        }
    }
}

extern "C" void kernel_launch(void* const* d_in, const int* in_sizes, int n_in,
                              void* d_out, int out_size)
{
    const float* key   = (const float*)d_in[0];
    const float* query = (const float*)d_in[1];
    const float* value = (const float*)d_in[2];
    const int*   qmask = (const int*)d_in[3];

    float* out_ctx  = (float*)d_out;
    float* out_attn = (float*)d_out + (size_t)BATCH * SEQ * DIM;

    pack_k_kernel<<<BATCH*SEQ*32/256, 256>>>(key);
    pack_v_kernel<<<BATCH*SEQ*16/256, 256>>>(value);

    cudaFuncSetAttribute(attn_mma_kernel,
                         cudaFuncAttributeMaxDynamicSharedMemorySize, SMEM_BYTES);
    dim3 grid(SEQ / TM, BATCH);
    attn_mma_kernel<<<grid, NTHR, SMEM_BYTES>>>(query, qmask, out_ctx, out_attn);
}

// round 16
// speedup vs baseline: 1.4702x; 1.4702x over previous
#include <cuda_runtime.h>
#include <cstdint>

#define BATCH 8
#define SEQ   2048
#define DIM   64
#define TM    64
#define TN    32
#define NTILES (SEQ/TN)   // 64
#define NTHR  256

// ---- smem layout (float offsets) ----
// K frag buffer: 32 keys x 36 float4 (32 data + 4 pad) = 4608 floats per buf
// V frag buffer: 4 groups x 128 float4 = 2048 floats per buf
#define KBUF4 1152
#define VBUF4 512
#define F_K   0
#define F_V   9216
#define F_SE  13312
#define F_MSK 15616
#define F_RS  17664
#define F_INV 17792
#define SMEM_FLOATS 17856
#define SMEM_BYTES (SMEM_FLOATS*4)
#define EST 36

// fragment-major scratch:
// g_kfrag[key][ks*4+c4] = {Khi[ks*8+c4], Khi[ks*8+c4+4], Klo[...], Klo[...]}
// g_vfrag[group][mt][r4][c4] = {Vt_hi[m][k], Vt_hi[m+8][k], Vt_hi[m][k+4], Vt_hi[m+8][k+4]}
__device__ float4 g_kfrag[BATCH*SEQ*32];
__device__ float4 g_vfrag[BATCH*SEQ*16];

__device__ __forceinline__ uint32_t tf32u(float x) {
    uint32_t u; asm("cvt.rna.tf32.f32 %0, %1;" : "=r"(u) : "f"(x)); return u;
}
__device__ __forceinline__ float uf(uint32_t u) { return __uint_as_float(u); }
__device__ __forceinline__ uint32_t fu(float f) { return __float_as_uint(f); }
__device__ __forceinline__ uint32_t s2u(const void* p) {
    uint32_t a;
    asm("{ .reg .u64 t; cvta.to.shared.u64 t, %1; cvt.u32.u64 %0, t; }" : "=r"(a) : "l"(p));
    return a;
}

#define CP16(dst, src) asm volatile("cp.async.ca.shared.global [%0], [%1], 16;" \
                                    :: "r"(dst), "l"(src) : "memory")
#define CP_COMMIT() asm volatile("cp.async.commit_group;" ::: "memory")
#define CP_WAIT0()  asm volatile("cp.async.wait_group 0;" ::: "memory")

__device__ __forceinline__ void mma8(float* c, const uint32_t* a, uint32_t b0, uint32_t b1) {
    asm volatile("mma.sync.aligned.m16n8k8.row.col.f32.tf32.tf32.f32 "
        "{%0,%1,%2,%3},{%4,%5,%6,%7},{%8,%9},{%0,%1,%2,%3};"
        : "+f"(c[0]), "+f"(c[1]), "+f"(c[2]), "+f"(c[3])
        : "r"(a[0]), "r"(a[1]), "r"(a[2]), "r"(a[3]), "r"(b0), "r"(b1));
}

// ---- prologue: pack K (hi+lo) and V (hi) into fragment-major gmem ----
__global__ void __launch_bounds__(256)
pack_k_kernel(const float* __restrict__ key)
{
    int i = blockIdx.x * 256 + threadIdx.x;      // f4 idx < BATCH*SEQ*32
    int bk = i >> 5, r = i & 31, ks = r >> 2, c4 = r & 3;
    float a = key[(size_t)bk * 64 + ks * 8 + c4];
    float bb = key[(size_t)bk * 64 + ks * 8 + c4 + 4];
    float ha = uf(tf32u(a)), hb = uf(tf32u(bb));
    g_kfrag[i] = make_float4(ha, hb, a - ha, bb - hb);
}
__global__ void __launch_bounds__(256)
pack_v_kernel(const float* __restrict__ value)
{
    int i = blockIdx.x * 256 + threadIdx.x;      // f4 idx < BATCH*SEQ*16
    int g = i >> 7, r = i & 127, mt = r >> 5, rr = r & 31, r4 = rr >> 2, c4 = rr & 3;
    const float* vb = value + (size_t)g * 8 * 64;
    float x0 = vb[c4 * 64 + mt * 16 + r4];
    float x1 = vb[c4 * 64 + mt * 16 + r4 + 8];
    float x2 = vb[(c4 + 4) * 64 + mt * 16 + r4];
    float x3 = vb[(c4 + 4) * 64 + mt * 16 + r4 + 8];
    g_vfrag[i] = make_float4(uf(tf32u(x0)), uf(tf32u(x1)), uf(tf32u(x2)), uf(tf32u(x3)));
}

// stage fragment tile nt via cp.async into buffer nt&1
__device__ __forceinline__ void stage(uint32_t sb, int b, int nt, int t) {
    const int buf = nt & 1;
    const float4* ksrc = g_kfrag + ((size_t)b * SEQ + nt * TN) * 32;
    const float4* vsrc = g_vfrag + (size_t)b * SEQ * 16 + (size_t)nt * 512;
    #pragma unroll
    for (int i = 0; i < 4; i++) {
        int idx = t + NTHR * i;                  // 0..1023
        int kk = idx >> 5, j = idx & 31;
        CP16(sb + (buf * KBUF4 + kk * 36 + j) * 16, ksrc + idx);
    }
    #pragma unroll
    for (int i = 0; i < 2; i++) {
        int idx = t + NTHR * i;                  // 0..511
        CP16(sb + F_V * 4 + (buf * VBUF4 + idx) * 16, vsrc + idx);
    }
}

__global__ void __launch_bounds__(NTHR, 2)
attn_mma_kernel(const float* __restrict__ query,
                const int*   __restrict__ qmask,
                float* __restrict__ out_ctx,
                float*              out_attn)
{
    extern __shared__ float sm[];
    const uint32_t sb = s2u(sm);
    const int b  = blockIdx.y;
    const int q0 = blockIdx.x * TM;
    const int t  = threadIdx.x;
    const int w  = t >> 5;
    const int wqg = w >> 1;          // q group 0..3 (16 rows each)
    const int kh  = w & 1;           // key half 0/1 (16 keys each)
    const int lane = t & 31;
    const int r4 = lane >> 2;        // 0..7
    const int c4 = lane & 3;         // 0..3

    float* attn_base = out_attn + ((size_t)b * SEQ + q0) * SEQ;

    // ---- stage tile 0 (async), mask ----
    stage(sb, b, 0, t);
    CP_COMMIT();
    {
        const int* mg = qmask + (size_t)b * SEQ;
        float* msk = sm + F_MSK;
        #pragma unroll
        for (int i = t; i < SEQ; i += NTHR)
            msk[i] = mg[i] ? -1e30f : 0.0f;
    }

    // ---- persistent Q frags (hi only, scaled 0.125) ----
    uint32_t qh[8][4];
    {
        const float* qr = query + ((size_t)b * SEQ + q0 + 16 * wqg) * DIM;
        #pragma unroll
        for (int ks = 0; ks < 8; ks++) {
            qh[ks][0] = tf32u(qr[(size_t)r4 * DIM + ks * 8 + c4] * 0.125f);
            qh[ks][1] = tf32u(qr[(size_t)(r4 + 8) * DIM + ks * 8 + c4] * 0.125f);
            qh[ks][2] = tf32u(qr[(size_t)r4 * DIM + ks * 8 + c4 + 4] * 0.125f);
            qh[ks][3] = tf32u(qr[(size_t)(r4 + 8) * DIM + ks * 8 + c4 + 4] * 0.125f);
        }
    }

    float cacc[4][2][4];             // ctx^T partial over this key half
    #pragma unroll
    for (int mt = 0; mt < 4; mt++)
        #pragma unroll
        for (int nq = 0; nq < 2; nq++)
            #pragma unroll
            for (int i = 0; i < 4; i++) cacc[mt][nq][i] = 0.0f;
    float rs0 = 0.0f, rs8 = 0.0f;

    float* sE = sm + F_SE;
    const float* msk = sm + F_MSK;

    for (int kt = 0; kt < NTILES; kt++) {
        const int buf = kt & 1;
        CP_WAIT0();
        __syncthreads();             // tile kt visible; prev compute done
        if (kt + 1 < NTILES) {
            stage(sb, b, kt + 1, t);
            CP_COMMIT();
        }

        // ---- QK^T: S[16q x 16key(half)], 2-term tf32, frag-major LDS.128 ----
        float sacc[2][4];
        #pragma unroll
        for (int nt = 0; nt < 2; nt++)
            #pragma unroll
            for (int i = 0; i < 4; i++) sacc[nt][i] = 0.0f;

        const float4* kf = (const float4*)sm + buf * KBUF4
                         + (kh * 16 + r4) * 36 + c4;
        #pragma unroll
        for (int ks = 0; ks < 8; ks++) {
            #pragma unroll
            for (int nt = 0; nt < 2; nt++) {
                float4 f = kf[nt * 288 + ks * 4];
                mma8(sacc[nt], qh[ks], fu(f.x), fu(f.y));
                mma8(sacc[nt], qh[ks], fu(f.z), fu(f.w));
            }
        }

        // ---- epilogue: exp+mask -> gmem + sE, rowsum ----
        {
            float* ar0 = attn_base + (size_t)(16 * wqg + r4) * SEQ + kt * TN;
            float* ar8 = ar0 + (size_t)8 * SEQ;
            float* se0 = sE + (16 * wqg + r4) * EST;
            float* se8 = se0 + 8 * EST;
            #pragma unroll
            for (int nt = 0; nt < 2; nt++) {
                int kloc = kh * 16 + nt * 8 + 2 * c4;
                float m0 = msk[kt * TN + kloc];
                float m1 = msk[kt * TN + kloc + 1];
                float e0 = __expf(sacc[nt][0] + m0);
                float e1 = __expf(sacc[nt][1] + m1);
                float e2 = __expf(sacc[nt][2] + m0);
                float e3 = __expf(sacc[nt][3] + m1);
                rs0 += e0 + e1; rs8 += e2 + e3;
                *(float2*)(ar0 + kloc) = make_float2(e0, e1);
                *(float2*)(ar8 + kloc) = make_float2(e2, e3);
                *(float2*)(se0 + kloc) = make_float2(e0, e1);
                *(float2*)(se8 + kloc) = make_float2(e2, e3);
            }
        }
        __syncwarp();

        // ---- PV (transposed, own key half, 1-term): ctx^T += Vhi^T * Phi^T ----
        {
            const float4* vf = (const float4*)sm + F_V / 4 + buf * VBUF4
                             + (kh * 2) * 128 + r4 * 4 + c4;
            const float* se_b = sE + (16 * wqg + r4) * EST + kh * 16 + c4;
            #pragma unroll
            for (int ks = 0; ks < 2; ks++) {
                uint32_t bh[2][2];
                #pragma unroll
                for (int nq = 0; nq < 2; nq++) {
                    bh[nq][0] = tf32u(se_b[nq * 8 * EST + ks * 8]);
                    bh[nq][1] = tf32u(se_b[nq * 8 * EST + ks * 8 + 4]);
                }
                #pragma unroll
                for (int mt = 0; mt < 4; mt++) {
                    float4 a = vf[ks * 128 + mt * 32];
                    uint32_t ah[4] = {fu(a.x), fu(a.y), fu(a.z), fu(a.w)};
                    #pragma unroll
                    for (int nq = 0; nq < 2; nq++)
                        mma8(cacc[mt][nq], ah, bh[nq][0], bh[nq][1]);
                }
            }
        }
    }
    __syncthreads();

    // ---- rowsum: quad-reduce, write per-half partials ----
    rs0 += __shfl_xor_sync(0xffffffffu, rs0, 1);
    rs0 += __shfl_xor_sync(0xffffffffu, rs0, 2);
    rs8 += __shfl_xor_sync(0xffffffffu, rs8, 1);
    rs8 += __shfl_xor_sync(0xffffffffu, rs8, 2);
    if (c4 == 0) {
        sm[F_RS + (16 * wqg + r4) * 2 + kh]     = rs0;
        sm[F_RS + (16 * wqg + r4 + 8) * 2 + kh] = rs8;
    }
    // ---- odd warps dump ctx partials (reuse K area) ----
    if (kh == 1) {
        float* dst = sm + F_K + wqg * 1024 + lane * 32;
        #pragma unroll
        for (int mt = 0; mt < 4; mt++)
            #pragma unroll
            for (int nq = 0; nq < 2; nq++)
                #pragma unroll
                for (int i = 0; i < 4; i++)
                    dst[mt * 8 + nq * 4 + i] = cacc[mt][nq][i];
    }
    __syncthreads();

    if (t < TM) sm[F_INV + t] = 1.0f / (sm[F_RS + t * 2] + sm[F_RS + t * 2 + 1]);
    if (kh == 0) {
        const float* src = sm + F_K + wqg * 1024 + lane * 32;
        #pragma unroll
        for (int mt = 0; mt < 4; mt++)
            #pragma unroll
            for (int nq = 0; nq < 2; nq++)
                #pragma unroll
                for (int i = 0; i < 4; i++)
                    cacc[mt][nq][i] += src[mt * 8 + nq * 4 + i];
    }
    __syncthreads();

    // ---- ctx out (even warps, normalized) ----
    if (kh == 0) {
        const float* sInv = sm + F_INV;
        #pragma unroll
        for (int nq = 0; nq < 2; nq++) {
            int qloc = 16 * wqg + nq * 8 + 2 * c4;
            float i0 = sInv[qloc], i1 = sInv[qloc + 1];
            float* o0 = out_ctx + ((size_t)b * SEQ + q0 + qloc) * DIM;
            float* o1 = o0 + DIM;
            #pragma unroll
            for (int mt = 0; mt < 4; mt++) {
                int dimr = mt * 16 + r4;
                o0[dimr]     = cacc[mt][nq][0] * i0;
                o1[dimr]     = cacc[mt][nq][1] * i1;
                o0[dimr + 8] = cacc[mt][nq][2] * i0;
                o1[dimr + 8] = cacc[mt][nq][3] * i1;
            }
        }
    }

    // ---- normalize this CTA's attn slab in place (L2-hot) ----
    {
        const float* sInv = sm + F_INV;
        #pragma unroll 4
        for (int i = t; i < TM * SEQ / 4; i += NTHR) {
            int r = i >> 9;            // / (SEQ/4)
            int c = i & 511;
            float inv = sInv[r];
            float4* p = (float4*)(attn_base + (size_t)r * SEQ) + c;
            float4 v = *p;
            v.x *= inv; v.y *= inv; v.z *= inv; v.w *= inv;
            *p = v;
        }
    }
}

extern "C" void kernel_launch(void* const* d_in, const int* in_sizes, int n_in,
                              void* d_out, int out_size)
{
    const float* key   = (const float*)d_in[0];
    const float* query = (const float*)d_in[1];
    const float* value = (const float*)d_in[2];
    const int*   qmask = (const int*)d_in[3];

    float* out_ctx  = (float*)d_out;
    float* out_attn = (float*)d_out + (size_t)BATCH * SEQ * DIM;

    pack_k_kernel<<<BATCH*SEQ*32/256, 256>>>(key);
    pack_v_kernel<<<BATCH*SEQ*16/256, 256>>>(value);

    cudaFuncSetAttribute(attn_mma_kernel,
                         cudaFuncAttributeMaxDynamicSharedMemorySize, SMEM_BYTES);
    dim3 grid(SEQ / TM, BATCH);
    attn_mma_kernel<<<grid, NTHR, SMEM_BYTES>>>(query, qmask, out_ctx, out_attn);
}

// round 17
// speedup vs baseline: 1.5741x; 1.0707x over previous
#include <cuda_runtime.h>
#include <cuda_bf16.h>
#include <cstdint>

#define BATCH 8
#define SEQ   2048
#define DIM   64
#define TM    64
#define TN    32
#define NTILES (SEQ/TN)   // 64
#define NTHR  256

// ---- smem layout (float offsets) ----
// K frag buffer: 32 keys x 18 float4 (16 data + 2 pad) = 2304 floats per buf
// V frag buffer: 512 float4 = 2048 floats per buf
#define KBUF4 576
#define VBUF4 512
#define F_K   0
#define F_V   4608
#define F_SE  8704
#define F_MSK 11008
#define F_RS  13056
#define F_INV 13184
#define SMEM_FLOATS 13248
#define SMEM_BYTES (SMEM_FLOATS*4)
#define EST 36

// fragment-major scratch:
// g_kfrag[key][ks*4+c4] = {b0h, b1h, b0l, b1l} bf16x2 pairs for m16n8k16 B-frag
//   b0 = {K[n][ks*16+2c4], K[n][ks*16+2c4+1]}, b1 = same +8
// g_vfrag[group][mt][r4][c4] = tf32 {Vt[m][k], Vt[m+8][k], Vt[m][k+4], Vt[m+8][k+4]}
__device__ uint4  g_kfrag[BATCH*SEQ*16];
__device__ float4 g_vfrag[BATCH*SEQ*16];

__device__ __forceinline__ uint32_t tf32u(float x) {
    uint32_t u; asm("cvt.rna.tf32.f32 %0, %1;" : "=r"(u) : "f"(x)); return u;
}
__device__ __forceinline__ float uf(uint32_t u) { return __uint_as_float(u); }
__device__ __forceinline__ uint32_t fu(float f) { return __float_as_uint(f); }
__device__ __forceinline__ uint32_t s2u(const void* p) {
    uint32_t a;
    asm("{ .reg .u64 t; cvta.to.shared.u64 t, %1; cvt.u32.u64 %0, t; }" : "=r"(a) : "l"(p));
    return a;
}

// split (a,b) into packed bf16x2 hi and residual bf16x2 lo
__device__ __forceinline__ void bfsplit2(float a, float b, uint32_t& hi, uint32_t& lo) {
    __nv_bfloat16 ha = __float2bfloat16_rn(a), hb = __float2bfloat16_rn(b);
    __nv_bfloat162 hp; hp.x = ha; hp.y = hb;
    hi = *reinterpret_cast<uint32_t*>(&hp);
    __nv_bfloat16 la = __float2bfloat16_rn(a - __bfloat162float(ha));
    __nv_bfloat16 lb = __float2bfloat16_rn(b - __bfloat162float(hb));
    __nv_bfloat162 lp; lp.x = la; lp.y = lb;
    lo = *reinterpret_cast<uint32_t*>(&lp);
}

#define CP16(dst, src) asm volatile("cp.async.ca.shared.global [%0], [%1], 16;" \
                                    :: "r"(dst), "l"(src) : "memory")
#define CP_COMMIT() asm volatile("cp.async.commit_group;" ::: "memory")
#define CP_WAIT0()  asm volatile("cp.async.wait_group 0;" ::: "memory")

// bf16 k16 mma: D += A(16x16 bf16) * B(16x8 bf16)
__device__ __forceinline__ void mma16(float* c, const uint32_t* a, uint32_t b0, uint32_t b1) {
    asm volatile("mma.sync.aligned.m16n8k16.row.col.f32.bf16.bf16.f32 "
        "{%0,%1,%2,%3},{%4,%5,%6,%7},{%8,%9},{%0,%1,%2,%3};"
        : "+f"(c[0]), "+f"(c[1]), "+f"(c[2]), "+f"(c[3])
        : "r"(a[0]), "r"(a[1]), "r"(a[2]), "r"(a[3]), "r"(b0), "r"(b1));
}
// tf32 k8 mma
__device__ __forceinline__ void mma8(float* c, const uint32_t* a, uint32_t b0, uint32_t b1) {
    asm volatile("mma.sync.aligned.m16n8k8.row.col.f32.tf32.tf32.f32 "
        "{%0,%1,%2,%3},{%4,%5,%6,%7},{%8,%9},{%0,%1,%2,%3};"
        : "+f"(c[0]), "+f"(c[1]), "+f"(c[2]), "+f"(c[3])
        : "r"(a[0]), "r"(a[1]), "r"(a[2]), "r"(a[3]), "r"(b0), "r"(b1));
}

// ---- prologue: pack K bf16 hi/lo frags; V tf32-hi frags ----
__global__ void __launch_bounds__(256)
pack_k_kernel(const float* __restrict__ key)
{
    int i = blockIdx.x * 256 + threadIdx.x;      // < BATCH*SEQ*16
    int kk = i >> 4, r = i & 15, ks = r >> 2, c4 = r & 3;
    const float* kp = key + (size_t)kk * 64 + ks * 16 + 2 * c4;
    uint32_t b0h, b0l, b1h, b1l;
    bfsplit2(kp[0], kp[1], b0h, b0l);
    bfsplit2(kp[8], kp[9], b1h, b1l);
    g_kfrag[i] = make_uint4(b0h, b1h, b0l, b1l);
}
__global__ void __launch_bounds__(256)
pack_v_kernel(const float* __restrict__ value)
{
    int i = blockIdx.x * 256 + threadIdx.x;      // < BATCH*SEQ*16
    int g = i >> 7, r = i & 127, mt = r >> 5, rr = r & 31, r4 = rr >> 2, c4 = rr & 3;
    const float* vb = value + (size_t)g * 8 * 64;
    float x0 = vb[c4 * 64 + mt * 16 + r4];
    float x1 = vb[c4 * 64 + mt * 16 + r4 + 8];
    float x2 = vb[(c4 + 4) * 64 + mt * 16 + r4];
    float x3 = vb[(c4 + 4) * 64 + mt * 16 + r4 + 8];
    g_vfrag[i] = make_float4(uf(tf32u(x0)), uf(tf32u(x1)), uf(tf32u(x2)), uf(tf32u(x3)));
}

// stage fragment tile nt via cp.async into buffer nt&1
__device__ __forceinline__ void stage(uint32_t sb, int b, int nt, int t) {
    const int buf = nt & 1;
    const uint4*  ksrc = g_kfrag + ((size_t)b * SEQ + nt * TN) * 16;
    const float4* vsrc = g_vfrag + (size_t)b * SEQ * 16 + (size_t)nt * 512;
    #pragma unroll
    for (int i = 0; i < 2; i++) {
        int idx = t + NTHR * i;                  // 0..511
        int kk = idx >> 4, j = idx & 15;
        CP16(sb + (buf * KBUF4 + kk * 18 + j) * 16, ksrc + idx);
        CP16(sb + F_V * 4 + (buf * VBUF4 + idx) * 16, vsrc + idx);
    }
}

__global__ void __launch_bounds__(NTHR, 2)
attn_mma_kernel(const float* __restrict__ query,
                const int*   __restrict__ qmask,
                float* __restrict__ out_ctx,
                float*              out_attn)
{
    extern __shared__ float sm[];
    const uint32_t sb = s2u(sm);
    const int b  = blockIdx.y;
    const int q0 = blockIdx.x * TM;
    const int t  = threadIdx.x;
    const int w  = t >> 5;
    const int wqg = w >> 1;          // q group 0..3 (16 rows each)
    const int kh  = w & 1;           // key half 0/1 (16 keys each)
    const int lane = t & 31;
    const int r4 = lane >> 2;        // 0..7
    const int c4 = lane & 3;         // 0..3

    float* attn_base = out_attn + ((size_t)b * SEQ + q0) * SEQ;

    // ---- stage tile 0 (async), mask ----
    stage(sb, b, 0, t);
    CP_COMMIT();
    {
        const int* mg = qmask + (size_t)b * SEQ;
        float* msk = sm + F_MSK;
        #pragma unroll
        for (int i = t; i < SEQ; i += NTHR)
            msk[i] = mg[i] ? -1e30f : 0.0f;
    }

    // ---- persistent Q frags: bf16 hi/lo, scaled 0.125 (A of m16n8k16) ----
    uint32_t qhi[4][4], qlo[4][4];
    {
        const float* qr = query + ((size_t)b * SEQ + q0 + 16 * wqg) * DIM;
        #pragma unroll
        for (int ks = 0; ks < 4; ks++) {
            int d = ks * 16 + 2 * c4;
            const float* p0 = qr + (size_t)r4 * DIM + d;        // row r4
            const float* p1 = qr + (size_t)(r4 + 8) * DIM + d;  // row r4+8
            bfsplit2(p0[0] * 0.125f, p0[1] * 0.125f, qhi[ks][0], qlo[ks][0]);
            bfsplit2(p1[0] * 0.125f, p1[1] * 0.125f, qhi[ks][1], qlo[ks][1]);
            bfsplit2(p0[8] * 0.125f, p0[9] * 0.125f, qhi[ks][2], qlo[ks][2]);
            bfsplit2(p1[8] * 0.125f, p1[9] * 0.125f, qhi[ks][3], qlo[ks][3]);
        }
    }

    float cacc[4][2][4];             // ctx^T partial over this key half
    #pragma unroll
    for (int mt = 0; mt < 4; mt++)
        #pragma unroll
        for (int nq = 0; nq < 2; nq++)
            #pragma unroll
            for (int i = 0; i < 4; i++) cacc[mt][nq][i] = 0.0f;
    float rs0 = 0.0f, rs8 = 0.0f;

    float* sE = sm + F_SE;
    const float* msk = sm + F_MSK;

    for (int kt = 0; kt < NTILES; kt++) {
        const int buf = kt & 1;
        CP_WAIT0();
        __syncthreads();             // tile kt visible; prev compute done
        if (kt + 1 < NTILES) {
            stage(sb, b, kt + 1, t);
            CP_COMMIT();
        }

        // ---- QK^T: S[16q x 16key(half)], bf16x3 on m16n8k16 ----
        float sacc[2][4];
        #pragma unroll
        for (int nt = 0; nt < 2; nt++)
            #pragma unroll
            for (int i = 0; i < 4; i++) sacc[nt][i] = 0.0f;

        const float4* kf = (const float4*)sm + buf * KBUF4
                         + (kh * 16 + r4) * 18 + c4;
        #pragma unroll
        for (int ks = 0; ks < 4; ks++) {
            #pragma unroll
            for (int nt = 0; nt < 2; nt++) {
                float4 f = kf[nt * 144 + ks * 4];   // {b0h,b1h,b0l,b1l}
                mma16(sacc[nt], qhi[ks], fu(f.x), fu(f.y));
                mma16(sacc[nt], qhi[ks], fu(f.z), fu(f.w));
                mma16(sacc[nt], qlo[ks], fu(f.x), fu(f.y));
            }
        }

        // ---- epilogue: exp+mask -> gmem + sE, rowsum ----
        {
            float* ar0 = attn_base + (size_t)(16 * wqg + r4) * SEQ + kt * TN;
            float* ar8 = ar0 + (size_t)8 * SEQ;
            float* se0 = sE + (16 * wqg + r4) * EST;
            float* se8 = se0 + 8 * EST;
            #pragma unroll
            for (int nt = 0; nt < 2; nt++) {
                int kloc = kh * 16 + nt * 8 + 2 * c4;
                float m0 = msk[kt * TN + kloc];
                float m1 = msk[kt * TN + kloc + 1];
                float e0 = __expf(sacc[nt][0] + m0);
                float e1 = __expf(sacc[nt][1] + m1);
                float e2 = __expf(sacc[nt][2] + m0);
                float e3 = __expf(sacc[nt][3] + m1);
                rs0 += e0 + e1; rs8 += e2 + e3;
                *(float2*)(ar0 + kloc) = make_float2(e0, e1);
                *(float2*)(ar8 + kloc) = make_float2(e2, e3);
                *(float2*)(se0 + kloc) = make_float2(e0, e1);
                *(float2*)(se8 + kloc) = make_float2(e2, e3);
            }
        }
        __syncwarp();

        // ---- PV (transposed, own key half, 1-term tf32): ctx^T += Vhi^T * Phi^T ----
        {
            const float4* vf = (const float4*)sm + F_V / 4 + buf * VBUF4
                             + kh * 256 + r4 * 4 + c4;
            const float* se_b = sE + (16 * wqg + r4) * EST + kh * 16 + c4;
            #pragma unroll
            for (int ks = 0; ks < 2; ks++) {
                uint32_t bh[2][2];
                #pragma unroll
                for (int nq = 0; nq < 2; nq++) {
                    bh[nq][0] = tf32u(se_b[nq * 8 * EST + ks * 8]);
                    bh[nq][1] = tf32u(se_b[nq * 8 * EST + ks * 8 + 4]);
                }
                #pragma unroll
                for (int mt = 0; mt < 4; mt++) {
                    float4 a = vf[ks * 128 + mt * 32];
                    uint32_t ah[4] = {fu(a.x), fu(a.y), fu(a.z), fu(a.w)};
                    #pragma unroll
                    for (int nq = 0; nq < 2; nq++)
                        mma8(cacc[mt][nq], ah, bh[nq][0], bh[nq][1]);
                }
            }
        }
    }
    __syncthreads();

    // ---- rowsum: quad-reduce, write per-half partials ----
    rs0 += __shfl_xor_sync(0xffffffffu, rs0, 1);
    rs0 += __shfl_xor_sync(0xffffffffu, rs0, 2);
    rs8 += __shfl_xor_sync(0xffffffffu, rs8, 1);
    rs8 += __shfl_xor_sync(0xffffffffu, rs8, 2);
    if (c4 == 0) {
        sm[F_RS + (16 * wqg + r4) * 2 + kh]     = rs0;
        sm[F_RS + (16 * wqg + r4 + 8) * 2 + kh] = rs8;
    }
    // ---- odd warps dump ctx partials (reuse K area) ----
    if (kh == 1) {
        float* dst = sm + F_K + wqg * 1024 + lane * 32;
        #pragma unroll
        for (int mt = 0; mt < 4; mt++)
            #pragma unroll
            for (int nq = 0; nq < 2; nq++)
                #pragma unroll
                for (int i = 0; i < 4; i++)
                    dst[mt * 8 + nq * 4 + i] = cacc[mt][nq][i];
    }
    __syncthreads();

    if (t < TM) sm[F_INV + t] = 1.0f / (sm[F_RS + t * 2] + sm[F_RS + t * 2 + 1]);
    if (kh == 0) {
        const float* src = sm + F_K + wqg * 1024 + lane * 32;
        #pragma unroll
        for (int mt = 0; mt < 4; mt++)
            #pragma unroll
            for (int nq = 0; nq < 2; nq++)
                #pragma unroll
                for (int i = 0; i < 4; i++)
                    cacc[mt][nq][i] += src[mt * 8 + nq * 4 + i];
    }
    __syncthreads();

    // ---- ctx out (even warps, normalized) ----
    if (kh == 0) {
        const float* sInv = sm + F_INV;
        #pragma unroll
        for (int nq = 0; nq < 2; nq++) {
            int qloc = 16 * wqg + nq * 8 + 2 * c4;
            float i0 = sInv[qloc], i1 = sInv[qloc + 1];
            float* o0 = out_ctx + ((size_t)b * SEQ + q0 + qloc) * DIM;
            float* o1 = o0 + DIM;
            #pragma unroll
            for (int mt = 0; mt < 4; mt++) {
                int dimr = mt * 16 + r4;
                o0[dimr]     = cacc[mt][nq][0] * i0;
                o1[dimr]     = cacc[mt][nq][1] * i1;
                o0[dimr + 8] = cacc[mt][nq][2] * i0;
                o1[dimr + 8] = cacc[mt][nq][3] * i1;
            }
        }
    }

    // ---- normalize this CTA's attn slab in place (L2-hot) ----
    {
        const float* sInv = sm + F_INV;
        #pragma unroll 4
        for (int i = t; i < TM * SEQ / 4; i += NTHR) {
            int r = i >> 9;            // / (SEQ/4)
            int c = i & 511;
            float inv = sInv[r];
            float4* p = (float4*)(attn_base + (size_t)r * SEQ) + c;
            float4 v = *p;
            v.x *= inv; v.y *= inv; v.z *= inv; v.w *= inv;
            *p = v;
        }
    }
}

extern "C" void kernel_launch(void* const* d_in, const int* in_sizes, int n_in,
                              void* d_out, int out_size)
{
    const float* key   = (const float*)d_in[0];
    const float* query = (const float*)d_in[1];
    const float* value = (const float*)d_in[2];
    const int*   qmask = (const int*)d_in[3];

    float* out_ctx  = (float*)d_out;
    float* out_attn = (float*)d_out + (size_t)BATCH * SEQ * DIM;

    pack_k_kernel<<<BATCH*SEQ*16/256, 256>>>(key);
    pack_v_kernel<<<BATCH*SEQ*16/256, 256>>>(value);

    cudaFuncSetAttribute(attn_mma_kernel,
                         cudaFuncAttributeMaxDynamicSharedMemorySize, SMEM_BYTES);
    dim3 grid(SEQ / TM, BATCH);
    attn_mma_kernel<<<grid, NTHR, SMEM_BYTES>>>(query, qmask, out_ctx, out_attn);
}